// round 5
// baseline (speedup 1.0000x reference)
#include <cuda_runtime.h>
#include <cuda_bf16.h>
#include <math.h>

// ---------------- problem constants ----------------
#define Bb    64
#define Ss    1024
#define Dd    256
#define Hh    256
#define H2    512
#define Ff    128
#define Tt    64
#define Ll    8
#define NSEG  128
#define DIN   1152
#define G4    2048           // 4 * H2
#define NROWS 65536          // B * S
#define NSEGT 8192           // B * NSEG

// ---------------- scratch (static device, no allocs) ----------------
__device__ float g_decin[NSEGT * DIN];
__device__ float g_U[(size_t)NROWS * 768];
__device__ float g_Wall[768 * Dd];
__device__ float g_gx[(size_t)NSEGT * G4];
__device__ float g_h[(size_t)129 * Bb * H2];            // fp32 h (for logits GEMM)
__device__ __nv_bfloat16 g_hb[(size_t)129 * Bb * H2];   // bf16 h (for recurrence)
__device__ unsigned g_bar2[2];

// ---------------- helpers ----------------
__device__ __forceinline__ float sigmf(float x) { return 1.f / (1.f + __expf(-x)); }
__device__ __forceinline__ float tanhfast(float x) { return 2.f / (1.f + __expf(-2.f * x)) - 1.f; }
__device__ __forceinline__ unsigned packbf(float lo, float hi) {
    unsigned d;
    asm("cvt.rn.bf16x2.f32 %0, %1, %2;" : "=r"(d) : "f"(hi), "f"(lo));
    return d;
}

#define MMA_TF32(acc, a0, a1, a2, a3, b0, b1)                                  \
    asm("mma.sync.aligned.m16n8k8.row.col.f32.tf32.tf32.f32 "                  \
        "{%0,%1,%2,%3},{%4,%5,%6,%7},{%8,%9},{%0,%1,%2,%3};"                   \
        : "+f"(acc[0]), "+f"(acc[1]), "+f"(acc[2]), "+f"(acc[3])               \
        : "r"(a0), "r"(a1), "r"(a2), "r"(a3), "r"(b0), "r"(b1))

#define MMA_BF16(acc, a0, a1, a2, a3, b0, b1)                                  \
    asm("mma.sync.aligned.m16n8k16.row.col.f32.bf16.bf16.f32 "                 \
        "{%0,%1,%2,%3},{%4,%5,%6,%7},{%8,%9},{%0,%1,%2,%3};"                   \
        : "+f"(acc[0]), "+f"(acc[1]), "+f"(acc[2]), "+f"(acc[3])               \
        : "r"(a0), "r"(a1), "r"(a2), "r"(a3), "r"(b0), "r"(b1))

#define LDSM_X4(r0, r1, r2, r3, addr)                                          \
    asm volatile("ldmatrix.sync.aligned.m8n8.x4.shared.b16 {%0,%1,%2,%3}, [%4];" \
                 : "=r"(r0), "=r"(r1), "=r"(r2), "=r"(r3) : "r"(addr))

#define CP_ASYNC16(dst, src)                                                   \
    asm volatile("cp.async.cg.shared.global [%0], [%1], 16;\n" ::              \
                 "r"(dst), "l"(src))

// ================= 128x128 double-buffered tf32 GEMM (LDSM, no CVT) =========
#define HBM 128
#define HBN 128
#define HBK 32
#define HSP 36
#define GEMM3_SMEM ((2 * HBM * HSP + 2 * HBN * HSP) * 4)   // 73728 B

__global__ __launch_bounds__(256, 2) void gemm3(
    const float* __restrict__ A, const float* __restrict__ Bw,
    float* __restrict__ C, int M, int N, int K,
    const int* __restrict__ gather)
{
    extern __shared__ unsigned gsm[];
    unsigned* AsAll = gsm;
    unsigned* BsAll = gsm + 2 * HBM * HSP;
    __shared__ int rows_s[HBM];

    int tid = threadIdx.x;
    int mBase = blockIdx.y * HBM, nBase = blockIdx.x * HBN;
    if (tid < HBM) rows_s[tid] = gather ? gather[mBase + tid] : (mBase + tid);
    __syncthreads();

    int w = tid >> 5, lane = tid & 31;
    int grp = lane >> 2, tig = lane & 3;
    int wm = w & 1, wn = w >> 1;

    unsigned asmem = (unsigned)__cvta_generic_to_shared(AsAll);
    unsigned bsmem = (unsigned)__cvta_generic_to_shared(BsAll);
    unsigned aAddr0 = asmem + (unsigned)((wm * 64 + (lane & 15)) * (HSP * 4) + ((lane >> 4) << 4));
    unsigned bAddr0 = bsmem + (unsigned)((wn * 32 + ((lane >> 4) << 3) + (lane & 7)) * (HSP * 4)
                                         + (((lane >> 3) & 1) << 4));

    float acc[4][4][4];
#pragma unroll
    for (int mt = 0; mt < 4; mt++)
#pragma unroll
        for (int nt = 0; nt < 4; nt++)
#pragma unroll
            for (int i = 0; i < 4; i++) acc[mt][nt][i] = 0.f;

    int nkt = K / HBK;

#define GLOAD3(s, kt) do {                                                      \
        int koff = (kt) * HBK;                                                  \
        _Pragma("unroll")                                                       \
        for (int i = 0; i < 4; i++) {                                           \
            int cid = tid + i * 256;                                            \
            int row = cid >> 3, ch = (cid & 7) * 4;                             \
            const float* src = A + (size_t)rows_s[row] * K + koff + ch;         \
            unsigned dst = (unsigned)__cvta_generic_to_shared(                  \
                &AsAll[(s) * HBM * HSP + row * HSP + ch]);                      \
            CP_ASYNC16(dst, src);                                               \
        }                                                                       \
        _Pragma("unroll")                                                       \
        for (int i = 0; i < 4; i++) {                                           \
            int cid = tid + i * 256;                                            \
            int row = cid >> 3, ch = (cid & 7) * 4;                             \
            const float* src = Bw + (size_t)(nBase + row) * K + koff + ch;      \
            unsigned dst = (unsigned)__cvta_generic_to_shared(                  \
                &BsAll[(s) * HBN * HSP + row * HSP + ch]);                      \
            CP_ASYNC16(dst, src);                                               \
        }                                                                       \
        asm volatile("cp.async.commit_group;\n");                               \
    } while (0)

    GLOAD3(0, 0);

    for (int kt = 0; kt < nkt; kt++) {
        int s = kt & 1;
        if (kt + 1 < nkt) {
            GLOAD3((kt + 1) & 1, kt + 1);
            asm volatile("cp.async.wait_group 1;\n" ::: "memory");
        } else {
            asm volatile("cp.async.wait_group 0;\n" ::: "memory");
        }
        __syncthreads();

        unsigned aS = aAddr0 + (unsigned)(s * HBM * HSP * 4);
        unsigned bS = bAddr0 + (unsigned)(s * HBN * HSP * 4);
#pragma unroll
        for (int ks = 0; ks < 4; ks++) {
            unsigned kb = ks * 32;
            unsigned bfr[2][4];
#pragma unroll
            for (int ntp = 0; ntp < 2; ntp++)
                LDSM_X4(bfr[ntp][0], bfr[ntp][1], bfr[ntp][2], bfr[ntp][3],
                        bS + ntp * (16 * HSP * 4) + kb);
#pragma unroll
            for (int mt = 0; mt < 4; mt++) {
                unsigned a0, a1, a2, a3;
                LDSM_X4(a0, a1, a2, a3, aS + mt * (16 * HSP * 4) + kb);
                MMA_TF32(acc[mt][0], a0, a1, a2, a3, bfr[0][0], bfr[0][1]);
                MMA_TF32(acc[mt][1], a0, a1, a2, a3, bfr[0][2], bfr[0][3]);
                MMA_TF32(acc[mt][2], a0, a1, a2, a3, bfr[1][0], bfr[1][1]);
                MMA_TF32(acc[mt][3], a0, a1, a2, a3, bfr[1][2], bfr[1][3]);
            }
        }
        __syncthreads();
    }

#pragma unroll
    for (int mt = 0; mt < 4; mt++) {
        int row0 = mBase + wm * 64 + mt * 16 + grp;
#pragma unroll
        for (int nt = 0; nt < 4; nt++) {
            int col = nBase + wn * 32 + nt * 8 + tig * 2;
            *(float2*)&C[(size_t)row0 * N + col] = make_float2(acc[mt][nt][0], acc[mt][nt][1]);
            *(float2*)&C[(size_t)(row0 + 8) * N + col] = make_float2(acc[mt][nt][2], acc[mt][nt][3]);
        }
    }
}

// ================= 128x64 GEMM (logits) — LDSM, no CVT =================
#define GBM 128
#define GBN 64
#define GSP 36
#define GEMM2_SMEM ((2 * GBM * GSP + 2 * GBN * GSP) * 4)   // 55296 B

__global__ __launch_bounds__(256, 2) void gemm2(
    const float* __restrict__ A, const float* __restrict__ Bw,
    float* __restrict__ C, int M, int N, int K)
{
    extern __shared__ unsigned gsm[];
    unsigned* AsAll = gsm;
    unsigned* BsAll = gsm + 2 * GBM * GSP;

    int tid = threadIdx.x;
    int mBase = blockIdx.y * GBM, nBase = blockIdx.x * GBN;

    int w = tid >> 5, lane = tid & 31;
    int grp = lane >> 2, tig = lane & 3;
    int wm = w & 3, wn = w >> 2;

    unsigned asmem = (unsigned)__cvta_generic_to_shared(AsAll);
    unsigned bsmem = (unsigned)__cvta_generic_to_shared(BsAll);
    unsigned aAddr0 = asmem + (unsigned)((wm * 32 + (lane & 15)) * (GSP * 4) + ((lane >> 4) << 4));
    unsigned bAddr0 = bsmem + (unsigned)((wn * 32 + ((lane >> 4) << 3) + (lane & 7)) * (GSP * 4)
                                         + (((lane >> 3) & 1) << 4));

    float acc[2][4][4];
#pragma unroll
    for (int mt = 0; mt < 2; mt++)
#pragma unroll
        for (int nt = 0; nt < 4; nt++)
#pragma unroll
            for (int i = 0; i < 4; i++) acc[mt][nt][i] = 0.f;

    int nkt = K / HBK;

#define GLOAD2(s, kt) do {                                                      \
        int koff = (kt) * HBK;                                                  \
        _Pragma("unroll")                                                       \
        for (int i = 0; i < 4; i++) {                                           \
            int cid = tid + i * 256;                                            \
            int row = cid >> 3, ch = (cid & 7) * 4;                             \
            const float* src = A + (size_t)(mBase + row) * K + koff + ch;       \
            unsigned dst = (unsigned)__cvta_generic_to_shared(                  \
                &AsAll[(s) * GBM * GSP + row * GSP + ch]);                      \
            CP_ASYNC16(dst, src);                                               \
        }                                                                       \
        _Pragma("unroll")                                                       \
        for (int i = 0; i < 2; i++) {                                           \
            int cid = tid + i * 256;                                            \
            int row = cid >> 3, ch = (cid & 7) * 4;                             \
            const float* src = Bw + (size_t)(nBase + row) * K + koff + ch;      \
            unsigned dst = (unsigned)__cvta_generic_to_shared(                  \
                &BsAll[(s) * GBN * GSP + row * GSP + ch]);                      \
            CP_ASYNC16(dst, src);                                               \
        }                                                                       \
        asm volatile("cp.async.commit_group;\n");                               \
    } while (0)

    GLOAD2(0, 0);

    for (int kt = 0; kt < nkt; kt++) {
        int s = kt & 1;
        if (kt + 1 < nkt) {
            GLOAD2((kt + 1) & 1, kt + 1);
            asm volatile("cp.async.wait_group 1;\n" ::: "memory");
        } else {
            asm volatile("cp.async.wait_group 0;\n" ::: "memory");
        }
        __syncthreads();

        unsigned aS = aAddr0 + (unsigned)(s * GBM * GSP * 4);
        unsigned bS = bAddr0 + (unsigned)(s * GBN * GSP * 4);
#pragma unroll
        for (int ks = 0; ks < 4; ks++) {
            unsigned kb = ks * 32;
            unsigned bfr[2][4];
#pragma unroll
            for (int ntp = 0; ntp < 2; ntp++)
                LDSM_X4(bfr[ntp][0], bfr[ntp][1], bfr[ntp][2], bfr[ntp][3],
                        bS + ntp * (16 * GSP * 4) + kb);
#pragma unroll
            for (int mt = 0; mt < 2; mt++) {
                unsigned a0, a1, a2, a3;
                LDSM_X4(a0, a1, a2, a3, aS + mt * (16 * GSP * 4) + kb);
                MMA_TF32(acc[mt][0], a0, a1, a2, a3, bfr[0][0], bfr[0][1]);
                MMA_TF32(acc[mt][1], a0, a1, a2, a3, bfr[0][2], bfr[0][3]);
                MMA_TF32(acc[mt][2], a0, a1, a2, a3, bfr[1][0], bfr[1][1]);
                MMA_TF32(acc[mt][3], a0, a1, a2, a3, bfr[1][2], bfr[1][3]);
            }
        }
        __syncthreads();
    }

#pragma unroll
    for (int mt = 0; mt < 2; mt++) {
        int row0 = mBase + wm * 32 + mt * 16 + grp;
#pragma unroll
        for (int nt = 0; nt < 4; nt++) {
            int col = nBase + wn * 32 + nt * 8 + tig * 2;
            *(float2*)&C[(size_t)row0 * N + col] = make_float2(acc[mt][nt][0], acc[mt][nt][1]);
            *(float2*)&C[(size_t)(row0 + 8) * N + col] = make_float2(acc[mt][nt][2], acc[mt][nt][3]);
        }
    }
}

// ---------------- pack conv weights into [768,256] ----------------
__global__ void pack_wall(const float* __restrict__ w1, const float* __restrict__ w2,
                          const float* __restrict__ w3)
{
    int n = blockIdx.x, k4 = threadIdx.x;
    const float* src;
    if (n < 128)       src = w1 + n * Dd;
    else if (n < 384) { int m = n - 128; src = w2 + ((m & 127) * 2 + (m >> 7)) * Dd; }
    else              { int m = n - 384; src = w3 + ((m & 127) * 3 + (m >> 7)) * Dd; }
    ((float4*)(g_Wall + n * Dd))[k4] = ((const float4*)src)[k4];
}

// ---------------- segment features ----------------
__global__ __launch_bounds__(256) void seg_feat(
    const int* __restrict__ word_ids, const float* __restrict__ embed,
    const float* __restrict__ enc)
{
    int r = blockIdx.x;
    int b = r >> 7, seg = r & 127;
    __shared__ int ids[8];
    int tid = threadIdx.x;
    if (tid < 8) ids[tid] = word_ids[b * Ss + seg * Ll + tid];
    __syncthreads();
    {
        float s = 0.f;
#pragma unroll
        for (int t = 0; t < 8; t++) s += embed[(size_t)ids[t] * Dd + tid];
        g_decin[(size_t)r * DIN + tid] = s * 0.125f;
    }
    for (int k = tid; k < H2; k += 256) {
        float s = 0.f;
#pragma unroll
        for (int t = 0; t < 8; t++) s += enc[(size_t)(b * Ss + seg * Ll + t) * H2 + k];
        g_decin[(size_t)r * DIN + Dd + k] = s * 0.125f;
    }
}

// ---------------- conv tap-sum + relu + maxpool ----------------
__global__ __launch_bounds__(128) void conv_reduce(
    const float* __restrict__ b1, const float* __restrict__ b2, const float* __restrict__ b3)
{
    int r = blockIdx.x, f = threadIdx.x;
    const float* U = g_U + (size_t)r * 8 * 768;
    float m1 = -1e30f, m2 = -1e30f, m3 = -1e30f;
#pragma unroll
    for (int t = 0; t < 8; t++) m1 = fmaxf(m1, U[t * 768 + f]);
#pragma unroll
    for (int t = 0; t < 7; t++) m2 = fmaxf(m2, U[t * 768 + 128 + f] + U[(t + 1) * 768 + 256 + f]);
#pragma unroll
    for (int t = 0; t < 6; t++)
        m3 = fmaxf(m3, U[t * 768 + 384 + f] + U[(t + 1) * 768 + 512 + f] + U[(t + 2) * 768 + 640 + f]);
    float* d = g_decin + (size_t)r * DIN + 768;
    d[f]       = fmaxf(m1 + b1[f], 0.f);
    d[128 + f] = fmaxf(m2 + b2[f], 0.f);
    d[256 + f] = fmaxf(m3 + b3[f], 0.f);
}

// ---------------- h0 (bf16) + barrier reset ----------------
__global__ void h0_kernel(const float* __restrict__ enc)
{
    if (blockIdx.x == 0 && threadIdx.x < 2) g_bar2[threadIdx.x] = 0;
    int b = blockIdx.x;
    for (int j = threadIdx.x; j < H2; j += blockDim.x) {
        float v = (j < Hh) ? enc[(size_t)(b * Ss + Ss - 1) * H2 + j]
                           : enc[(size_t)(b * Ss) * H2 + j];
        g_hb[(size_t)b * H2 + j] = __float2bfloat16(v);
    }
}

// ================= bf16 scan, accumulator == gates =================
// 64 CTAs = 2 batch-groups x 32 unit-groups (16 units). 16 warps/CTA.
// Warp (mt = w&1 row-half, nt = w>>1 unit-pair). Column c of warp tile:
// unit = j0 + nt*2 + (c>>2), gate = c&3 (gate-interleaved layout).
// Full K=512 per warp -> no cross-warp reduction; lane^1 shfl merges
// {i,f}/{g,o}. Each of 512 lanes owns one (row, unit) cell.
#define SCP5 520
#define SCAN5_SMEM (32 * SCP5 * 2)   // 33280 B

__global__ __launch_bounds__(512, 1) void scan5(const float* __restrict__ Whh)
{
    extern __shared__ __nv_bfloat16 hA[];    // [32][520]

    int tid = threadIdx.x;
    int lane = tid & 31, w = tid >> 5;
    int grp = lane >> 2, tig = lane & 3;
    int mt = w & 1, nt = w >> 1;             // nt 0..7
    int cid = blockIdx.x;                    // 64 CTAs
    int bg = cid & 1;
    int j0 = (cid >> 1) * 16;

    // B fragments (n-index = grp): W row = gate(grp&3)*H2 + unit(j0+nt*2+(grp>>2))
    unsigned bw[32][2];
    {
        const float* wr = Whh + (size_t)((grp & 3) * H2 + j0 + nt * 2 + (grp >> 2)) * H2;
#pragma unroll
        for (int kc = 0; kc < 32; kc++) {
            const float* p = wr + kc * 16 + tig * 2;
            bw[kc][0] = packbf(p[0], p[1]);
            bw[kc][1] = packbf(p[8], p[9]);
        }
    }

    // lane's output cell: C cols 2tig,2tig+1 at rows grp, grp+8
    int isIF = ((tig & 1) == 0);
    int unit_l = j0 + nt * 2 + (tig >> 1);
    int row_l = mt * 16 + grp + (isIF ? 0 : 8);
    int row_global = bg * 32 + row_l;
    size_t gx_base = (size_t)row_global * NSEG * G4 + (size_t)unit_l;

    unsigned hA_u32 = (unsigned)__cvta_generic_to_shared(hA);
    unsigned ldbase = hA_u32 + (unsigned)((mt * 16 + (lane & 15)) * (SCP5 * 2)
                                          + ((lane >> 4) << 4));
    // staging chunk for this thread: 4 chunks of 16B
    int srow[4], scol[4];
#pragma unroll
    for (int i = 0; i < 4; i++) {
        int idx = tid + i * 512;             // 0..2047
        srow[i] = idx >> 6;                  // 32 rows
        scol[i] = idx & 63;                  // 64 x 16B per row
    }

    const __nv_bfloat16* ghb = g_hb;
    unsigned* pcount = &g_bar2[bg];
    float c_st = 0.f;

    for (int t = 0; t < NSEG; t++) {
        // stage h_t rows bg*32..+31 (32KB) via cp.async
        {
            const __nv_bfloat16* src = ghb + (size_t)t * Bb * H2 + (size_t)bg * 32 * H2;
#pragma unroll
            for (int i = 0; i < 4; i++) {
                CP_ASYNC16(hA_u32 + (unsigned)(srow[i] * (SCP5 * 2) + scol[i] * 16),
                           src + srow[i] * H2 + scol[i] * 8);
            }
            asm volatile("cp.async.commit_group;\n");
        }

        // prefetch gates_x (independent of h)
        size_t gxo = gx_base + (size_t)t * G4;
        float gxi = __ldg(&g_gx[gxo]);
        float gxf = __ldg(&g_gx[gxo + 512]);
        float gxg = __ldg(&g_gx[gxo + 1024]);
        float gxq = __ldg(&g_gx[gxo + 1536]);

        asm volatile("cp.async.wait_group 0;\n" ::: "memory");
        __syncthreads();

        // full-K gates: 32 ldsm + 32 mma, accumulator = final partial-free gates
        float acc[4] = {0.f, 0.f, 0.f, 0.f};
#pragma unroll
        for (int kc = 0; kc < 32; kc++) {
            unsigned a0, a1, a2, a3;
            LDSM_X4(a0, a1, a2, a3, ldbase + kc * 32);
            MMA_BF16(acc, a0, a1, a2, a3, bw[kc][0], bw[kc][1]);
        }

        // lane-pair exchange: even lane (i,f rows grp), odd (g,o rows grp+8)
        float s0 = isIF ? acc[2] : acc[0];
        float s1 = isIF ? acc[3] : acc[1];
        float v0 = __shfl_xor_sync(0xffffffffu, s0, 1);
        float v1 = __shfl_xor_sync(0xffffffffu, s1, 1);
        float gi, gf, gg, go;
        if (isIF) { gi = acc[0]; gf = acc[1]; gg = v0; go = v1; }
        else      { gi = v0;     gf = v1;     gg = acc[2]; go = acc[3]; }
        gi += gxi; gf += gxf; gg += gxg; go += gxq;

        c_st = sigmf(gf) * c_st + sigmf(gi) * tanhfast(gg);
        float h = sigmf(go) * tanhfast(c_st);
        size_t ho = (size_t)(t + 1) * Bb * H2 + (size_t)row_global * H2 + unit_l;
        g_hb[ho] = __float2bfloat16(h);
        g_h[ho] = h;

        // per-batch-group barrier (32 CTAs), monotonic counter
        __syncthreads();
        if (tid == 0) {
            unsigned one = 1;
            asm volatile("red.release.gpu.global.add.u32 [%0], %1;"
                         :: "l"(pcount), "r"(one) : "memory");
            unsigned target = 32u * (unsigned)(t + 1);
            unsigned cur;
            do {
                asm volatile("ld.acquire.gpu.global.u32 %0, [%1];"
                             : "=r"(cur) : "l"(pcount));
            } while (cur < target);
        }
        __syncthreads();
    }
}

// ---------------- log_softmax + output permutation ----------------
__global__ void lsm_kernel(const float* __restrict__ logits, float* __restrict__ out)
{
    int r = blockIdx.x;              // t*64 + b
    int v = threadIdx.x;             // 64 threads
    float x = logits[(size_t)r * Tt + v];
    float m = x;
#pragma unroll
    for (int o = 16; o; o >>= 1) m = fmaxf(m, __shfl_xor_sync(0xffffffffu, m, o));
    __shared__ float s1[2], s2[2];
    if ((v & 31) == 0) s1[v >> 5] = m;
    __syncthreads();
    m = fmaxf(s1[0], s1[1]);
    float s = expf(x - m);
#pragma unroll
    for (int o = 16; o; o >>= 1) s += __shfl_xor_sync(0xffffffffu, s, o);
    if ((v & 31) == 0) s2[v >> 5] = s;
    __syncthreads();
    s = s2[0] + s2[1];
    int t = r >> 6, bb = r & 63;
    out[(size_t)(bb * NSEG + t) * Tt + v] = x - m - logf(s);
}

// ---------------- launcher ----------------
extern "C" void kernel_launch(void* const* d_in, const int* in_sizes, int n_in,
                              void* d_out, int out_size)
{
    const int*   word_ids = (const int*)d_in[0];
    const float* embed    = (const float*)d_in[1];
    const float* enc      = (const float*)d_in[2];
    const float* w1       = (const float*)d_in[3];
    const float* b1       = (const float*)d_in[4];
    const float* w2       = (const float*)d_in[5];
    const float* b2       = (const float*)d_in[6];
    const float* w3       = (const float*)d_in[7];
    const float* b3       = (const float*)d_in[8];
    const float* Wih      = (const float*)d_in[9];
    const float* Whh      = (const float*)d_in[10];
    const float* Wfc      = (const float*)d_in[11];
    float* out = (float*)d_out;

    void *pU, *pWall, *pDecin, *pGx, *pH, *pLog;
    cudaGetSymbolAddress(&pU, g_U);
    cudaGetSymbolAddress(&pWall, g_Wall);
    cudaGetSymbolAddress(&pDecin, g_decin);
    cudaGetSymbolAddress(&pGx, g_gx);
    cudaGetSymbolAddress(&pH, g_h);
    pLog = pU;   // g_U dead after conv_reduce

    cudaFuncSetAttribute(gemm3, cudaFuncAttributeMaxDynamicSharedMemorySize, GEMM3_SMEM);
    cudaFuncSetAttribute(gemm2, cudaFuncAttributeMaxDynamicSharedMemorySize, GEMM2_SMEM);
    cudaFuncSetAttribute(scan5, cudaFuncAttributeMaxDynamicSharedMemorySize, SCAN5_SMEM);

    pack_wall<<<768, 64>>>(w1, w2, w3);
    seg_feat<<<NSEGT, 256>>>(word_ids, embed, enc);

    // conv taps: U[65536,768] = gather(embed) @ Wall^T
    gemm3<<<dim3(768 / HBN, NROWS / HBM), 256, GEMM3_SMEM>>>(
        embed, (const float*)pWall, (float*)pU, NROWS, 768, Dd, word_ids);
    conv_reduce<<<NSEGT, 128>>>(b1, b2, b3);

    // gates_x[8192,2048] = dec_in @ W_ih^T
    gemm3<<<dim3(G4 / HBN, NSEGT / HBM), 256, GEMM3_SMEM>>>(
        (const float*)pDecin, Wih, (float*)pGx, NSEGT, G4, DIN, nullptr);

    h0_kernel<<<Bb, 256>>>(enc);

    scan5<<<64, 512, SCAN5_SMEM>>>(Whh);

    // logits[8192,64] = h(1..128) @ W_fc^T
    gemm2<<<dim3(Tt / GBN, NSEGT / GBM), 256, GEMM2_SMEM>>>(
        (const float*)pH + (size_t)Bb * H2, Wfc, (float*)pLog, NSEGT, Tt, H2);

    lsm_kernel<<<NSEGT, Tt>>>((const float*)pLog, out);
}

// round 6
// speedup vs baseline: 1.1943x; 1.1943x over previous
#include <cuda_runtime.h>
#include <cuda_bf16.h>
#include <math.h>

// ---------------- problem constants ----------------
#define Bb    64
#define Ss    1024
#define Dd    256
#define Hh    256
#define H2    512
#define Ff    128
#define Tt    64
#define Ll    8
#define NSEG  128
#define DIN   1152
#define G4    2048           // 4 * H2
#define NROWS 65536          // B * S
#define NSEGT 8192           // B * NSEG

// ---------------- scratch (static device, no allocs) ----------------
__device__ __nv_bfloat16 g_decinb[NSEGT * DIN];          // bf16 dec_in
__device__ __nv_bfloat16 g_U[(size_t)NROWS * 768];       // bf16 conv taps
__device__ float g_Wall[768 * Dd];
__device__ __nv_bfloat16 g_Wihb[(size_t)G4 * DIN];       // bf16 W_ih
__device__ float g_gx[(size_t)NSEGT * G4];
__device__ float g_h[(size_t)129 * Bb * H2];             // fp32 h (logits GEMM)
__device__ __nv_bfloat16 g_hb[(size_t)129 * Bb * H2];    // bf16 h (recurrence)
__device__ unsigned g_bar2[2];

// ---------------- helpers ----------------
__device__ __forceinline__ float sigmf(float x) { return 1.f / (1.f + __expf(-x)); }
__device__ __forceinline__ float tanhfast(float x) { return 2.f / (1.f + __expf(-2.f * x)) - 1.f; }
__device__ __forceinline__ unsigned packbf(float lo, float hi) {
    unsigned d;
    asm("cvt.rn.bf16x2.f32 %0, %1, %2;" : "=r"(d) : "f"(hi), "f"(lo));
    return d;
}

#define MMA_TF32(acc, a0, a1, a2, a3, b0, b1)                                  \
    asm("mma.sync.aligned.m16n8k8.row.col.f32.tf32.tf32.f32 "                  \
        "{%0,%1,%2,%3},{%4,%5,%6,%7},{%8,%9},{%0,%1,%2,%3};"                   \
        : "+f"(acc[0]), "+f"(acc[1]), "+f"(acc[2]), "+f"(acc[3])               \
        : "r"(a0), "r"(a1), "r"(a2), "r"(a3), "r"(b0), "r"(b1))

#define MMA_BF16(acc, a0, a1, a2, a3, b0, b1)                                  \
    asm("mma.sync.aligned.m16n8k16.row.col.f32.bf16.bf16.f32 "                 \
        "{%0,%1,%2,%3},{%4,%5,%6,%7},{%8,%9},{%0,%1,%2,%3};"                   \
        : "+f"(acc[0]), "+f"(acc[1]), "+f"(acc[2]), "+f"(acc[3])               \
        : "r"(a0), "r"(a1), "r"(a2), "r"(a3), "r"(b0), "r"(b1))

#define LDSM_X4(r0, r1, r2, r3, addr)                                          \
    asm volatile("ldmatrix.sync.aligned.m8n8.x4.shared.b16 {%0,%1,%2,%3}, [%4];" \
                 : "=r"(r0), "=r"(r1), "=r"(r2), "=r"(r3) : "r"(addr))

#define CP_ASYNC16(dst, src)                                                   \
    asm volatile("cp.async.cg.shared.global [%0], [%1], 16;\n" ::              \
                 "r"(dst), "l"(src))

// ================= 128x128 tf32 GEMM, bf16 output (conv taps) =================
#define HBM 128
#define HBN 128
#define HBK 32
#define HSP 36
#define GEMM3_SMEM ((2 * HBM * HSP + 2 * HBN * HSP) * 4)   // 73728 B

__global__ __launch_bounds__(256, 2) void gemm3(
    const float* __restrict__ A, const float* __restrict__ Bw,
    __nv_bfloat16* __restrict__ C, int M, int N, int K,
    const int* __restrict__ gather)
{
    extern __shared__ unsigned gsm[];
    unsigned* AsAll = gsm;
    unsigned* BsAll = gsm + 2 * HBM * HSP;
    __shared__ int rows_s[HBM];

    int tid = threadIdx.x;
    int mBase = blockIdx.y * HBM, nBase = blockIdx.x * HBN;
    if (tid < HBM) rows_s[tid] = gather ? gather[mBase + tid] : (mBase + tid);
    __syncthreads();

    int w = tid >> 5, lane = tid & 31;
    int grp = lane >> 2, tig = lane & 3;
    int wm = w & 1, wn = w >> 1;

    unsigned asmem = (unsigned)__cvta_generic_to_shared(AsAll);
    unsigned bsmem = (unsigned)__cvta_generic_to_shared(BsAll);
    unsigned aAddr0 = asmem + (unsigned)((wm * 64 + (lane & 15)) * (HSP * 4) + ((lane >> 4) << 4));
    unsigned bAddr0 = bsmem + (unsigned)((wn * 32 + ((lane >> 4) << 3) + (lane & 7)) * (HSP * 4)
                                         + (((lane >> 3) & 1) << 4));

    float acc[4][4][4];
#pragma unroll
    for (int mt = 0; mt < 4; mt++)
#pragma unroll
        for (int nt = 0; nt < 4; nt++)
#pragma unroll
            for (int i = 0; i < 4; i++) acc[mt][nt][i] = 0.f;

    int nkt = K / HBK;

#define GLOAD3(s, kt) do {                                                      \
        int koff = (kt) * HBK;                                                  \
        _Pragma("unroll")                                                       \
        for (int i = 0; i < 4; i++) {                                           \
            int cid = tid + i * 256;                                            \
            int row = cid >> 3, ch = (cid & 7) * 4;                             \
            const float* src = A + (size_t)rows_s[row] * K + koff + ch;         \
            unsigned dst = (unsigned)__cvta_generic_to_shared(                  \
                &AsAll[(s) * HBM * HSP + row * HSP + ch]);                      \
            CP_ASYNC16(dst, src);                                               \
        }                                                                       \
        _Pragma("unroll")                                                       \
        for (int i = 0; i < 4; i++) {                                           \
            int cid = tid + i * 256;                                            \
            int row = cid >> 3, ch = (cid & 7) * 4;                             \
            const float* src = Bw + (size_t)(nBase + row) * K + koff + ch;      \
            unsigned dst = (unsigned)__cvta_generic_to_shared(                  \
                &BsAll[(s) * HBN * HSP + row * HSP + ch]);                      \
            CP_ASYNC16(dst, src);                                               \
        }                                                                       \
        asm volatile("cp.async.commit_group;\n");                               \
    } while (0)

    GLOAD3(0, 0);

    for (int kt = 0; kt < nkt; kt++) {
        int s = kt & 1;
        if (kt + 1 < nkt) {
            GLOAD3((kt + 1) & 1, kt + 1);
            asm volatile("cp.async.wait_group 1;\n" ::: "memory");
        } else {
            asm volatile("cp.async.wait_group 0;\n" ::: "memory");
        }
        __syncthreads();

        unsigned aS = aAddr0 + (unsigned)(s * HBM * HSP * 4);
        unsigned bS = bAddr0 + (unsigned)(s * HBN * HSP * 4);
#pragma unroll
        for (int ks = 0; ks < 4; ks++) {
            unsigned kb = ks * 32;
            unsigned bfr[2][4];
#pragma unroll
            for (int ntp = 0; ntp < 2; ntp++)
                LDSM_X4(bfr[ntp][0], bfr[ntp][1], bfr[ntp][2], bfr[ntp][3],
                        bS + ntp * (16 * HSP * 4) + kb);
#pragma unroll
            for (int mt = 0; mt < 4; mt++) {
                unsigned a0, a1, a2, a3;
                LDSM_X4(a0, a1, a2, a3, aS + mt * (16 * HSP * 4) + kb);
                MMA_TF32(acc[mt][0], a0, a1, a2, a3, bfr[0][0], bfr[0][1]);
                MMA_TF32(acc[mt][1], a0, a1, a2, a3, bfr[0][2], bfr[0][3]);
                MMA_TF32(acc[mt][2], a0, a1, a2, a3, bfr[1][0], bfr[1][1]);
                MMA_TF32(acc[mt][3], a0, a1, a2, a3, bfr[1][2], bfr[1][3]);
            }
        }
        __syncthreads();
    }

#pragma unroll
    for (int mt = 0; mt < 4; mt++) {
        int row0 = mBase + wm * 64 + mt * 16 + grp;
#pragma unroll
        for (int nt = 0; nt < 4; nt++) {
            int col = nBase + wn * 32 + nt * 8 + tig * 2;
            *(unsigned*)&C[(size_t)row0 * N + col] = packbf(acc[mt][nt][0], acc[mt][nt][1]);
            *(unsigned*)&C[(size_t)(row0 + 8) * N + col] = packbf(acc[mt][nt][2], acc[mt][nt][3]);
        }
    }
}

// ================= 128x128 bf16 GEMM (gates): C fp32 = A_bf16 @ B_bf16^T ====
#define BBM 128
#define BBN 128
#define BBK 64
#define BSPH 72    // smem pitch in halves (144 B, conflict-free for ldsm)
#define GEMMB_SMEM (2 * (BBM + BBN) * BSPH * 2)   // 73728 B

__global__ __launch_bounds__(256, 2) void gemmb(
    const __nv_bfloat16* __restrict__ A, const __nv_bfloat16* __restrict__ Bw,
    float* __restrict__ C, int M, int N, int K)
{
    extern __shared__ unsigned short bsm[];

    int tid = threadIdx.x;
    int mBase = blockIdx.y * BBM, nBase = blockIdx.x * BBN;

    int w = tid >> 5, lane = tid & 31;
    int grp = lane >> 2, tig = lane & 3;
    int wm = w & 1, wn = w >> 1;       // 2x4 warp grid, warp tile 64x32

    unsigned smbase = (unsigned)__cvta_generic_to_shared(bsm);
    unsigned bbase = smbase + 2 * BBM * BSPH * 2;   // B region byte offset

    unsigned aAddr0 = smbase + (unsigned)((wm * 64 + (lane & 15)) * 144 + ((lane >> 4) << 4));
    unsigned bAddr0 = bbase + (unsigned)((wn * 32 + (lane & 15)) * 144 + ((lane >> 4) << 4));

    float acc[4][4][4];
#pragma unroll
    for (int mt = 0; mt < 4; mt++)
#pragma unroll
        for (int nt = 0; nt < 4; nt++)
#pragma unroll
            for (int i = 0; i < 4; i++) acc[mt][nt][i] = 0.f;

    int nkt = K / BBK;

#define BLOAD(s, kt) do {                                                       \
        int koff = (kt) * BBK;                                                  \
        _Pragma("unroll")                                                       \
        for (int i = 0; i < 4; i++) {                                           \
            int cid = tid + i * 256;                                            \
            int row = cid >> 3, ch = cid & 7;                                   \
            const __nv_bfloat16* src = A + (size_t)(mBase + row) * K + koff + ch * 8; \
            unsigned dst = smbase + (unsigned)(((s) * BBM + row) * 144 + ch * 16);    \
            CP_ASYNC16(dst, src);                                               \
        }                                                                       \
        _Pragma("unroll")                                                       \
        for (int i = 0; i < 4; i++) {                                           \
            int cid = tid + i * 256;                                            \
            int row = cid >> 3, ch = cid & 7;                                   \
            const __nv_bfloat16* src = Bw + (size_t)(nBase + row) * K + koff + ch * 8; \
            unsigned dst = bbase + (unsigned)(((s) * BBN + row) * 144 + ch * 16);     \
            CP_ASYNC16(dst, src);                                               \
        }                                                                       \
        asm volatile("cp.async.commit_group;\n");                               \
    } while (0)

    BLOAD(0, 0);

    for (int kt = 0; kt < nkt; kt++) {
        int s = kt & 1;
        if (kt + 1 < nkt) {
            BLOAD((kt + 1) & 1, kt + 1);
            asm volatile("cp.async.wait_group 1;\n" ::: "memory");
        } else {
            asm volatile("cp.async.wait_group 0;\n" ::: "memory");
        }
        __syncthreads();

        unsigned aS = aAddr0 + (unsigned)(s * BBM * 144);
        unsigned bS = bAddr0 + (unsigned)(s * BBN * 144);
#pragma unroll
        for (int kc = 0; kc < 4; kc++) {             // 4 x k16 chunks
            unsigned kb = kc * 32;                    // 32 B per k16
            unsigned bfr[2][4];
#pragma unroll
            for (int ntp = 0; ntp < 2; ntp++)
                LDSM_X4(bfr[ntp][0], bfr[ntp][1], bfr[ntp][2], bfr[ntp][3],
                        bS + ntp * (16 * 144) + kb);
            // ldsm matrices: m0=n0-7 klow, m1=n8-15 klow, m2=n0-7 khigh, m3=n8-15 khigh
#pragma unroll
            for (int mt = 0; mt < 4; mt++) {
                unsigned a0, a1, a2, a3;
                LDSM_X4(a0, a1, a2, a3, aS + mt * (16 * 144) + kb);
                MMA_BF16(acc[mt][0], a0, a1, a2, a3, bfr[0][0], bfr[0][2]);
                MMA_BF16(acc[mt][1], a0, a1, a2, a3, bfr[0][1], bfr[0][3]);
                MMA_BF16(acc[mt][2], a0, a1, a2, a3, bfr[1][0], bfr[1][2]);
                MMA_BF16(acc[mt][3], a0, a1, a2, a3, bfr[1][1], bfr[1][3]);
            }
        }
        __syncthreads();
    }

#pragma unroll
    for (int mt = 0; mt < 4; mt++) {
        int row0 = mBase + wm * 64 + mt * 16 + grp;
#pragma unroll
        for (int nt = 0; nt < 4; nt++) {
            int col = nBase + wn * 32 + nt * 8 + tig * 2;
            *(float2*)&C[(size_t)row0 * N + col] = make_float2(acc[mt][nt][0], acc[mt][nt][1]);
            *(float2*)&C[(size_t)(row0 + 8) * N + col] = make_float2(acc[mt][nt][2], acc[mt][nt][3]);
        }
    }
}

// ================= 128x64 tf32 GEMM (logits) =================
#define GBM 128
#define GBN 64
#define GSP 36
#define GEMM2_SMEM ((2 * GBM * GSP + 2 * GBN * GSP) * 4)   // 55296 B

__global__ __launch_bounds__(256, 2) void gemm2(
    const float* __restrict__ A, const float* __restrict__ Bw,
    float* __restrict__ C, int M, int N, int K)
{
    extern __shared__ unsigned gsm[];
    unsigned* AsAll = gsm;
    unsigned* BsAll = gsm + 2 * GBM * GSP;

    int tid = threadIdx.x;
    int mBase = blockIdx.y * GBM, nBase = blockIdx.x * GBN;

    int w = tid >> 5, lane = tid & 31;
    int grp = lane >> 2, tig = lane & 3;
    int wm = w & 3, wn = w >> 2;

    unsigned asmem = (unsigned)__cvta_generic_to_shared(AsAll);
    unsigned bsmem = (unsigned)__cvta_generic_to_shared(BsAll);
    unsigned aAddr0 = asmem + (unsigned)((wm * 32 + (lane & 15)) * (GSP * 4) + ((lane >> 4) << 4));
    unsigned bAddr0 = bsmem + (unsigned)((wn * 32 + ((lane >> 4) << 3) + (lane & 7)) * (GSP * 4)
                                         + (((lane >> 3) & 1) << 4));

    float acc[2][4][4];
#pragma unroll
    for (int mt = 0; mt < 2; mt++)
#pragma unroll
        for (int nt = 0; nt < 4; nt++)
#pragma unroll
            for (int i = 0; i < 4; i++) acc[mt][nt][i] = 0.f;

    int nkt = K / HBK;

#define GLOAD2(s, kt) do {                                                      \
        int koff = (kt) * HBK;                                                  \
        _Pragma("unroll")                                                       \
        for (int i = 0; i < 4; i++) {                                           \
            int cid = tid + i * 256;                                            \
            int row = cid >> 3, ch = (cid & 7) * 4;                             \
            const float* src = A + (size_t)(mBase + row) * K + koff + ch;       \
            unsigned dst = (unsigned)__cvta_generic_to_shared(                  \
                &AsAll[(s) * GBM * GSP + row * GSP + ch]);                      \
            CP_ASYNC16(dst, src);                                               \
        }                                                                       \
        _Pragma("unroll")                                                       \
        for (int i = 0; i < 2; i++) {                                           \
            int cid = tid + i * 256;                                            \
            int row = cid >> 3, ch = (cid & 7) * 4;                             \
            const float* src = Bw + (size_t)(nBase + row) * K + koff + ch;      \
            unsigned dst = (unsigned)__cvta_generic_to_shared(                  \
                &BsAll[(s) * GBN * GSP + row * GSP + ch]);                      \
            CP_ASYNC16(dst, src);                                               \
        }                                                                       \
        asm volatile("cp.async.commit_group;\n");                               \
    } while (0)

    GLOAD2(0, 0);

    for (int kt = 0; kt < nkt; kt++) {
        int s = kt & 1;
        if (kt + 1 < nkt) {
            GLOAD2((kt + 1) & 1, kt + 1);
            asm volatile("cp.async.wait_group 1;\n" ::: "memory");
        } else {
            asm volatile("cp.async.wait_group 0;\n" ::: "memory");
        }
        __syncthreads();

        unsigned aS = aAddr0 + (unsigned)(s * GBM * GSP * 4);
        unsigned bS = bAddr0 + (unsigned)(s * GBN * GSP * 4);
#pragma unroll
        for (int ks = 0; ks < 4; ks++) {
            unsigned kb = ks * 32;
            unsigned bfr[2][4];
#pragma unroll
            for (int ntp = 0; ntp < 2; ntp++)
                LDSM_X4(bfr[ntp][0], bfr[ntp][1], bfr[ntp][2], bfr[ntp][3],
                        bS + ntp * (16 * GSP * 4) + kb);
#pragma unroll
            for (int mt = 0; mt < 2; mt++) {
                unsigned a0, a1, a2, a3;
                LDSM_X4(a0, a1, a2, a3, aS + mt * (16 * GSP * 4) + kb);
                MMA_TF32(acc[mt][0], a0, a1, a2, a3, bfr[0][0], bfr[0][1]);
                MMA_TF32(acc[mt][1], a0, a1, a2, a3, bfr[0][2], bfr[0][3]);
                MMA_TF32(acc[mt][2], a0, a1, a2, a3, bfr[1][0], bfr[1][1]);
                MMA_TF32(acc[mt][3], a0, a1, a2, a3, bfr[1][2], bfr[1][3]);
            }
        }
        __syncthreads();
    }

#pragma unroll
    for (int mt = 0; mt < 2; mt++) {
        int row0 = mBase + wm * 32 + mt * 16 + grp;
#pragma unroll
        for (int nt = 0; nt < 4; nt++) {
            int col = nBase + wn * 32 + nt * 8 + tig * 2;
            *(float2*)&C[(size_t)row0 * N + col] = make_float2(acc[mt][nt][0], acc[mt][nt][1]);
            *(float2*)&C[(size_t)(row0 + 8) * N + col] = make_float2(acc[mt][nt][2], acc[mt][nt][3]);
        }
    }
}

// ---------------- pack conv weights + convert W_ih ----------------
__global__ void pack_wall(const float* __restrict__ w1, const float* __restrict__ w2,
                          const float* __restrict__ w3)
{
    int n = blockIdx.x, k4 = threadIdx.x;
    const float* src;
    if (n < 128)       src = w1 + n * Dd;
    else if (n < 384) { int m = n - 128; src = w2 + ((m & 127) * 2 + (m >> 7)) * Dd; }
    else              { int m = n - 384; src = w3 + ((m & 127) * 3 + (m >> 7)) * Dd; }
    ((float4*)(g_Wall + n * Dd))[k4] = ((const float4*)src)[k4];
}

__global__ void cvt_wih(const float* __restrict__ w)
{
    size_t i = ((size_t)blockIdx.x * 256 + threadIdx.x) * 4;
    float4 v = *(const float4*)(w + i);
    uint2 o = make_uint2(packbf(v.x, v.y), packbf(v.z, v.w));
    *(uint2*)((unsigned short*)g_Wihb + i) = o;
}

// ---------------- segment features (bf16 out) ----------------
__global__ __launch_bounds__(256) void seg_feat(
    const int* __restrict__ word_ids, const float* __restrict__ embed,
    const float* __restrict__ enc)
{
    int r = blockIdx.x;
    int b = r >> 7, seg = r & 127;
    __shared__ int ids[8];
    int tid = threadIdx.x;
    if (tid < 8) ids[tid] = word_ids[b * Ss + seg * Ll + tid];
    __syncthreads();
    {
        float s = 0.f;
#pragma unroll
        for (int t = 0; t < 8; t++) s += embed[(size_t)ids[t] * Dd + tid];
        g_decinb[(size_t)r * DIN + tid] = __float2bfloat16(s * 0.125f);
    }
    for (int k = tid; k < H2; k += 256) {
        float s = 0.f;
#pragma unroll
        for (int t = 0; t < 8; t++) s += enc[(size_t)(b * Ss + seg * Ll + t) * H2 + k];
        g_decinb[(size_t)r * DIN + Dd + k] = __float2bfloat16(s * 0.125f);
    }
}

// ---------------- conv tap-sum + relu + maxpool (bf16 in/out) ----------------
__global__ __launch_bounds__(128) void conv_reduce(
    const float* __restrict__ b1, const float* __restrict__ b2, const float* __restrict__ b3)
{
    int r = blockIdx.x, f = threadIdx.x;
    const __nv_bfloat16* U = g_U + (size_t)r * 8 * 768;
    float m1 = -1e30f, m2 = -1e30f, m3 = -1e30f;
#pragma unroll
    for (int t = 0; t < 8; t++) m1 = fmaxf(m1, __bfloat162float(U[t * 768 + f]));
#pragma unroll
    for (int t = 0; t < 7; t++)
        m2 = fmaxf(m2, __bfloat162float(U[t * 768 + 128 + f]) +
                       __bfloat162float(U[(t + 1) * 768 + 256 + f]));
#pragma unroll
    for (int t = 0; t < 6; t++)
        m3 = fmaxf(m3, __bfloat162float(U[t * 768 + 384 + f]) +
                       __bfloat162float(U[(t + 1) * 768 + 512 + f]) +
                       __bfloat162float(U[(t + 2) * 768 + 640 + f]));
    __nv_bfloat16* d = g_decinb + (size_t)r * DIN + 768;
    d[f]       = __float2bfloat16(fmaxf(m1 + b1[f], 0.f));
    d[128 + f] = __float2bfloat16(fmaxf(m2 + b2[f], 0.f));
    d[256 + f] = __float2bfloat16(fmaxf(m3 + b3[f], 0.f));
}

// ---------------- h0 (bf16) + barrier reset ----------------
__global__ void h0_kernel(const float* __restrict__ enc)
{
    if (blockIdx.x == 0 && threadIdx.x < 2) g_bar2[threadIdx.x] = 0;
    int b = blockIdx.x;
    for (int j = threadIdx.x; j < H2; j += blockDim.x) {
        float v = (j < Hh) ? enc[(size_t)(b * Ss + Ss - 1) * H2 + j]
                           : enc[(size_t)(b * Ss) * H2 + j];
        g_hb[(size_t)b * H2 + j] = __float2bfloat16(v);
    }
}

// ================= bf16 scan (scan4 + split barrier + gx pipeline) ==========
// 128 CTAs = 64 col-groups (8 units) x 2 batch-groups (32 rows); 16 warps.
// Warp (mt = w&1 row-half, kq = w>>1 K-slice of 64). Per-warp self-staging.
#define SCP 520
#define SCAN_SMEM (32 * SCP * 2 + 8 * 32 * 34 * 4)   // 68096 B

__global__ __launch_bounds__(512, 1) void scan6(const float* __restrict__ Whh)
{
    extern __shared__ unsigned ssm[];
    __nv_bfloat16* hA = (__nv_bfloat16*)ssm;                 // [32][520]
    float* pbuf = (float*)((char*)ssm + 32 * SCP * 2);       // [8][32][34]

    int tid = threadIdx.x;
    int lane = tid & 31, w = tid >> 5;
    int grp = lane >> 2, tig = lane & 3;
    int mt = w & 1, kq = w >> 1;
    int cid = blockIdx.x;
    int bg = cid & 1;
    int j0 = (cid >> 1) * 8;

    // W_hh bf16 fragments
    unsigned bw[4][4][2];
#pragma unroll
    for (int nt = 0; nt < 4; nt++) {
        const float* wr = Whh + (size_t)(nt * H2 + j0 + grp) * H2 + kq * 64;
#pragma unroll
        for (int kc = 0; kc < 4; kc++) {
            const float* p = wr + kc * 16 + tig * 2;
            bw[nt][kc][0] = packbf(p[0], p[1]);
            bw[nt][kc][1] = packbf(p[8], p[9]);
        }
    }

    const __nv_bfloat16* ghb = g_hb;
    unsigned* pcount = &g_bar2[bg];

    float c_st = 0.f;
    int b_hat = tid >> 3, jj = tid & 7;     // epilogue item (tid<256)
    int row_global = bg * 32 + b_hat;
    size_t gx_base = (size_t)(row_global * NSEG) * G4 + (size_t)(j0 + jj);

    unsigned hA_u32 = (unsigned)__cvta_generic_to_shared(hA);
    unsigned dstbase = hA_u32 + (unsigned)((mt * 16) * (SCP * 2) + kq * 128);
    unsigned ldbase = hA_u32 + (unsigned)((mt * 16 + (lane & 15)) * (SCP * 2)
                                          + kq * 128 + ((lane >> 4) << 4));

    // gx pipeline: preload t=0
    float gxi = 0.f, gxf = 0.f, gxg = 0.f, gxq = 0.f;
    if (tid < 256) {
        gxi = __ldg(&g_gx[gx_base]);
        gxf = __ldg(&g_gx[gx_base + 512]);
        gxg = __ldg(&g_gx[gx_base + 1024]);
        gxq = __ldg(&g_gx[gx_base + 1536]);
    }

    for (int t = 0; t < NSEG; t++) {
        // per-warp staging: own 16-row x 64-col slice (2KB)
        {
            const __nv_bfloat16* src = ghb + (size_t)t * Bb * H2
                                     + (size_t)(bg * 32 + mt * 16) * H2 + kq * 64;
#pragma unroll
            for (int i = 0; i < 4; i++) {
                int c = lane + 32 * i;
                int r = c >> 3, ch = c & 7;
                CP_ASYNC16(dstbase + (unsigned)(r * (SCP * 2) + ch * 16),
                           src + r * H2 + ch * 8);
            }
            asm volatile("cp.async.commit_group;\n");
        }
        asm volatile("cp.async.wait_group 0;\n" ::: "memory");
        __syncwarp();

        // [32 x 32] gate partial: 4 ldsm + 16 mma
        float acc[4][4];
#pragma unroll
        for (int nt = 0; nt < 4; nt++)
#pragma unroll
            for (int i = 0; i < 4; i++) acc[nt][i] = 0.f;
#pragma unroll
        for (int kc = 0; kc < 4; kc++) {
            unsigned a0, a1, a2, a3;
            LDSM_X4(a0, a1, a2, a3, ldbase + kc * 32);
#pragma unroll
            for (int nt = 0; nt < 4; nt++)
                MMA_BF16(acc[nt], a0, a1, a2, a3, bw[nt][kc][0], bw[nt][kc][1]);
        }
        {
            float* pb = pbuf + kq * (32 * 34);
            int row = mt * 16 + grp;
#pragma unroll
            for (int nt = 0; nt < 4; nt++) {
                int c0 = nt * 8 + tig * 2;
                pb[row * 34 + c0]           = acc[nt][0];
                pb[row * 34 + c0 + 1]       = acc[nt][1];
                pb[(row + 8) * 34 + c0]     = acc[nt][2];
                pb[(row + 8) * 34 + c0 + 1] = acc[nt][3];
            }
        }
        __syncthreads();

        if (tid < 256) {
            float gsum[4];
#pragma unroll
            for (int q = 0; q < 4; q++) {
                int col = q * 8 + jj;
                float s = 0.f;
#pragma unroll
                for (int k = 0; k < 8; k++) s += pbuf[k * (32 * 34) + b_hat * 34 + col];
                gsum[q] = s;
            }
            float gi = gsum[0] + gxi;
            float gf = gsum[1] + gxf;
            float gg = gsum[2] + gxg;
            float go = gsum[3] + gxq;
            c_st = sigmf(gf) * c_st + sigmf(gi) * tanhfast(gg);
            float h = sigmf(go) * tanhfast(c_st);
            size_t ho = (size_t)(t + 1) * Bb * H2 + (size_t)row_global * H2 + j0 + jj;
            g_hb[ho] = __float2bfloat16(h);
            g_h[ho] = h;

            // prefetch gx for t+1 — latency hides under the barrier
            if (t + 1 < NSEG) {
                size_t gxo = gx_base + (size_t)(t + 1) * G4;
                gxi = __ldg(&g_gx[gxo]);
                gxf = __ldg(&g_gx[gxo + 512]);
                gxg = __ldg(&g_gx[gxo + 1024]);
                gxq = __ldg(&g_gx[gxo + 1536]);
            }
        }

        // per-batch-group barrier (64 CTAs), monotonic counter
        __syncthreads();
        if (tid == 0) {
            unsigned one = 1;
            asm volatile("red.release.gpu.global.add.u32 [%0], %1;"
                         :: "l"(pcount), "r"(one) : "memory");
            unsigned target = 64u * (unsigned)(t + 1);
            unsigned cur;
            do {
                asm volatile("ld.acquire.gpu.global.u32 %0, [%1];"
                             : "=r"(cur) : "l"(pcount));
            } while (cur < target);
        }
        __syncthreads();
    }
}

// ---------------- log_softmax + output permutation ----------------
__global__ void lsm_kernel(const float* __restrict__ logits, float* __restrict__ out)
{
    int r = blockIdx.x;              // t*64 + b
    int v = threadIdx.x;             // 64 threads
    float x = logits[(size_t)r * Tt + v];
    float m = x;
#pragma unroll
    for (int o = 16; o; o >>= 1) m = fmaxf(m, __shfl_xor_sync(0xffffffffu, m, o));
    __shared__ float s1[2], s2[2];
    if ((v & 31) == 0) s1[v >> 5] = m;
    __syncthreads();
    m = fmaxf(s1[0], s1[1]);
    float s = expf(x - m);
#pragma unroll
    for (int o = 16; o; o >>= 1) s += __shfl_xor_sync(0xffffffffu, s, o);
    if ((v & 31) == 0) s2[v >> 5] = s;
    __syncthreads();
    s = s2[0] + s2[1];
    int t = r >> 6, bb = r & 63;
    out[(size_t)(bb * NSEG + t) * Tt + v] = x - m - logf(s);
}

// ---------------- launcher ----------------
extern "C" void kernel_launch(void* const* d_in, const int* in_sizes, int n_in,
                              void* d_out, int out_size)
{
    const int*   word_ids = (const int*)d_in[0];
    const float* embed    = (const float*)d_in[1];
    const float* enc      = (const float*)d_in[2];
    const float* w1       = (const float*)d_in[3];
    const float* b1       = (const float*)d_in[4];
    const float* w2       = (const float*)d_in[5];
    const float* b2       = (const float*)d_in[6];
    const float* w3       = (const float*)d_in[7];
    const float* b3       = (const float*)d_in[8];
    const float* Wih      = (const float*)d_in[9];
    const float* Whh      = (const float*)d_in[10];
    const float* Wfc      = (const float*)d_in[11];
    float* out = (float*)d_out;

    void *pU, *pWall, *pDecinb, *pWihb, *pGx, *pH;
    cudaGetSymbolAddress(&pU, g_U);
    cudaGetSymbolAddress(&pWall, g_Wall);
    cudaGetSymbolAddress(&pDecinb, g_decinb);
    cudaGetSymbolAddress(&pWihb, g_Wihb);
    cudaGetSymbolAddress(&pGx, g_gx);
    cudaGetSymbolAddress(&pH, g_h);
    float* pLog = (float*)pU;   // reuse g_U memory (dead after conv_reduce)

    cudaFuncSetAttribute(gemm3, cudaFuncAttributeMaxDynamicSharedMemorySize, GEMM3_SMEM);
    cudaFuncSetAttribute(gemmb, cudaFuncAttributeMaxDynamicSharedMemorySize, GEMMB_SMEM);
    cudaFuncSetAttribute(gemm2, cudaFuncAttributeMaxDynamicSharedMemorySize, GEMM2_SMEM);
    cudaFuncSetAttribute(scan6, cudaFuncAttributeMaxDynamicSharedMemorySize, SCAN_SMEM);

    pack_wall<<<768, 64>>>(w1, w2, w3);
    cvt_wih<<<(G4 * DIN) / 1024, 256>>>(Wih);
    seg_feat<<<NSEGT, 256>>>(word_ids, embed, enc);

    // conv taps: U_bf16[65536,768] = gather(embed) @ Wall^T (tf32)
    gemm3<<<dim3(768 / HBN, NROWS / HBM), 256, GEMM3_SMEM>>>(
        embed, (const float*)pWall, (__nv_bfloat16*)pU, NROWS, 768, Dd, word_ids);
    conv_reduce<<<NSEGT, 128>>>(b1, b2, b3);

    // gates_x[8192,2048] = dec_in_bf16 @ W_ih_bf16^T
    gemmb<<<dim3(G4 / BBN, NSEGT / BBM), 256, GEMMB_SMEM>>>(
        (const __nv_bfloat16*)pDecinb, (const __nv_bfloat16*)pWihb,
        (float*)pGx, NSEGT, G4, DIN);

    h0_kernel<<<Bb, 256>>>(enc);

    scan6<<<128, 512, SCAN_SMEM>>>(Whh);

    // logits[8192,64] = h(1..128) @ W_fc^T (tf32)
    gemm2<<<dim3(Tt / GBN, NSEGT / GBM), 256, GEMM2_SMEM>>>(
        (const float*)pH + (size_t)Bb * H2, Wfc, pLog, NSEGT, Tt, H2);

    lsm_kernel<<<NSEGT, Tt>>>((const float*)pLog, out);
}